// round 1
// baseline (speedup 1.0000x reference)
#include <cuda_runtime.h>
#include <cuda_bf16.h>

#define BB 2
#define SS 2048
#define DD 1024
#define HH 16
#define DKK 64
#define HW 32                  // half window: |i-j| <= 32
#define MM (BB*SS)             // 4096
#define KK DD                  // 1024

// Scratch (device globals: allocation-free rule)
__device__ float g_Q[(size_t)MM * DD];
__device__ float g_K[(size_t)MM * DD];
__device__ float g_V[(size_t)MM * DD];
__device__ float g_C[(size_t)MM * DD];

// ---------------------------------------------------------------------------
// Tiled fp32 GEMM: C[M,N] = A[M,K] @ W[N,K]^T (+ bias). 128x128 tile, BK=16,
// 256 threads, 8x8 per-thread microtile. M=4096, N=1024, K=1024 hardcoded.
// ---------------------------------------------------------------------------
__device__ __forceinline__ void gemm_body(const float* __restrict__ A,
                                          const float* __restrict__ W,
                                          float* __restrict__ C,
                                          const float* __restrict__ bias)
{
    __shared__ __align__(16) float As[16][128];
    __shared__ __align__(16) float Bs[16][128];

    const int tid  = threadIdx.x;
    const int tx   = tid & 15;
    const int ty   = tid >> 4;
    const int brow = blockIdx.y * 128;
    const int bcol = blockIdx.x * 128;

    float acc[8][8];
#pragma unroll
    for (int i = 0; i < 8; ++i)
#pragma unroll
        for (int j = 0; j < 8; ++j) acc[i][j] = 0.f;

    for (int k0 = 0; k0 < KK; k0 += 16) {
#pragma unroll
        for (int it = 0; it < 2; ++it) {
            int idx = tid + it * 256;            // 0..511 float4 slots
            int row = idx >> 2;                  // 0..127
            int c4  = (idx & 3) << 2;            // 0,4,8,12
            float4 a = *(const float4*)(A + (size_t)(brow + row) * KK + k0 + c4);
            As[c4 + 0][row] = a.x; As[c4 + 1][row] = a.y;
            As[c4 + 2][row] = a.z; As[c4 + 3][row] = a.w;
            float4 b = *(const float4*)(W + (size_t)(bcol + row) * KK + k0 + c4);
            Bs[c4 + 0][row] = b.x; Bs[c4 + 1][row] = b.y;
            Bs[c4 + 2][row] = b.z; Bs[c4 + 3][row] = b.w;
        }
        __syncthreads();
#pragma unroll
        for (int k = 0; k < 16; ++k) {
            float ra[8], rb[8];
            *(float4*)&ra[0] = *(const float4*)&As[k][ty * 8];
            *(float4*)&ra[4] = *(const float4*)&As[k][ty * 8 + 4];
            *(float4*)&rb[0] = *(const float4*)&Bs[k][tx * 8];
            *(float4*)&rb[4] = *(const float4*)&Bs[k][tx * 8 + 4];
#pragma unroll
            for (int i = 0; i < 8; ++i)
#pragma unroll
                for (int j = 0; j < 8; ++j)
                    acc[i][j] = fmaf(ra[i], rb[j], acc[i][j]);
        }
        __syncthreads();
    }

#pragma unroll
    for (int i = 0; i < 8; ++i) {
        int r = brow + ty * 8 + i;
#pragma unroll
        for (int j = 0; j < 8; j += 4) {
            int c = bcol + tx * 8 + j;
            float4 v;
            v.x = acc[i][j]; v.y = acc[i][j + 1];
            v.z = acc[i][j + 2]; v.w = acc[i][j + 3];
            if (bias) {
                v.x += bias[c];     v.y += bias[c + 1];
                v.z += bias[c + 2]; v.w += bias[c + 3];
            }
            *(float4*)(C + (size_t)r * DD + c) = v;
        }
    }
}

__global__ void __launch_bounds__(256) qkv_gemm(const float* __restrict__ q,
                                                const float* __restrict__ wq,
                                                const float* __restrict__ wk,
                                                const float* __restrict__ wv)
{
    const int z = blockIdx.z;
    const float* W = (z == 0) ? wq : ((z == 1) ? wk : wv);
    float* C = (z == 0) ? g_Q : ((z == 1) ? g_K : g_V);
    gemm_body(q, W, C, nullptr);
}

__global__ void __launch_bounds__(256) out_gemm(const float* __restrict__ wo,
                                                const float* __restrict__ bo,
                                                float* __restrict__ out)
{
    gemm_body(g_C, wo, out, bo);
}

// ---------------------------------------------------------------------------
// Local-window attention: one warp per (b,h,query). Lane l owns dims l, l+32.
// Online softmax over the <=65-key window; optional attn-prob band scatter.
// ---------------------------------------------------------------------------
__global__ void __launch_bounds__(128) attn_kernel(float* __restrict__ attn_out)
{
    __shared__ float sc[4][2 * HW + 1];

    const int warp = threadIdx.x >> 5;
    const int lane = threadIdx.x & 31;
    const int gq   = blockIdx.x * 4 + warp;    // 0 .. B*H*S-1
    const int i    = gq & (SS - 1);            // S = 2048 = 2^11
    const int bh   = gq >> 11;
    const int h    = bh & (HH - 1);
    const int b    = bh >> 4;

    const float* Qr = g_Q + (size_t)(b * SS + i) * DD + h * DKK;
    const float q0 = Qr[lane];
    const float q1 = Qr[lane + 32];

    const int jlo = max(0, i - HW);
    const int jhi = min(SS - 1, i + HW);
    const float scale = 0.125f;                // DK^-0.5

    float m = -1e30f, ssum = 0.f, a0 = 0.f, a1 = 0.f;

    for (int j = jlo; j <= jhi; ++j) {
        const size_t roff = (size_t)(b * SS + j) * DD + h * DKK;
        const float* Kr = g_K + roff;
        float p = q0 * Kr[lane] + q1 * Kr[lane + 32];
#pragma unroll
        for (int off = 16; off; off >>= 1) p += __shfl_xor_sync(0xffffffffu, p, off);
        const float s = p * scale;
        if (attn_out) sc[warp][j - jlo] = s;   // all lanes same value

        const float mn   = fmaxf(m, s);
        const float corr = __expf(m - mn);
        const float e    = __expf(s - mn);
        const float* Vr  = g_V + roff;
        a0   = a0 * corr + e * Vr[lane];
        a1   = a1 * corr + e * Vr[lane + 32];
        ssum = ssum * corr + e;
        m    = mn;
    }

    const float inv = 1.f / ssum;
    float* Cr = g_C + (size_t)(b * SS + i) * DD + h * DKK;
    Cr[lane]      = a0 * inv;
    Cr[lane + 32] = a1 * inv;

    if (attn_out) {
        __syncwarp();
        float* row = attn_out + ((size_t)((b * HH + h) * SS + i)) * SS;
        const int n = jhi - jlo + 1;
        for (int jj = lane; jj < n; jj += 32)
            row[jlo + jj] = __expf(sc[warp][jj] - m) * inv;
    }
}

// ---------------------------------------------------------------------------
extern "C" void kernel_launch(void* const* d_in, const int* in_sizes, int n_in,
                              void* d_out, int out_size)
{
    const float* q  = (const float*)d_in[0];
    const float* wq = (const float*)d_in[1];
    const float* wk = (const float*)d_in[2];
    const float* wv = (const float*)d_in[3];
    const float* wo = (const float*)d_in[4];
    const float* bo = (const float*)d_in[5];
    float* out = (float*)d_out;

    const size_t out_elems  = (size_t)BB * SS * DD;                 // 4,194,304
    const bool   write_attn = (size_t)out_size > out_elems;
    float* attn = out + out_elems;

    // QKV projections (grid.z selects wq/wk/wv)
    dim3 gq3(DD / 128, MM / 128, 3);
    qkv_gemm<<<gq3, 256>>>(q, wq, wk, wv);

    if (write_attn) {
        cudaMemsetAsync(attn, 0, (size_t)BB * HH * SS * SS * sizeof(float));
    }

    // Local attention (one warp per query)
    attn_kernel<<<(BB * HH * SS) / 4, 128>>>(write_attn ? attn : nullptr);

    // Output projection + bias
    dim3 go(DD / 128, MM / 128, 1);
    out_gemm<<<go, 256>>>(wo, bo, out);
}

// round 3
// speedup vs baseline: 1.7239x; 1.7239x over previous
#include <cuda_runtime.h>
#include <cuda_bf16.h>
#include <cstdint>

#define BB 2
#define SS 2048
#define DD 1024
#define HH 16
#define MM (BB*SS)             // 4096

// GEMM tiling
#define TM 128
#define TN 128
#define KC 64                  // bf16 elements per K chunk (128B rows)
#define NCH (DD/KC)            // 16
#define NSTAGE 3
#define STAGE_BYTES 65536      // 4 arrays x 128 rows x 128B
#define OFF_AHI 0
#define OFF_ALO 16384
#define OFF_BHI 32768
#define OFF_BLO 49152
#define GEMM_SMEM (NSTAGE*STAGE_BYTES)   // 196608

// Attention tiling
#define BQ 64
#define AROWS 128
#define ATT_SMEM ((AROWS*64*2 + 8*68)*4) // 67712

// ---------------------------------------------------------------------------
// Scratch (device globals: allocation-free rule)
// ---------------------------------------------------------------------------
__device__ float g_Q[(size_t)MM * DD];
__device__ float g_K[(size_t)MM * DD];
__device__ float g_V[(size_t)MM * DD];
__device__ __nv_bfloat16 g_Ahi[(size_t)MM * DD];
__device__ __nv_bfloat16 g_Alo[(size_t)MM * DD];
__device__ __nv_bfloat16 g_Whi[(size_t)4 * DD * DD];   // wq,wk,wv,wo
__device__ __nv_bfloat16 g_Wlo[(size_t)4 * DD * DD];
__device__ __nv_bfloat16 g_Chi[(size_t)MM * DD];
__device__ __nv_bfloat16 g_Clo[(size_t)MM * DD];

// ---------------------------------------------------------------------------
// Helpers
// ---------------------------------------------------------------------------
__device__ __forceinline__ uint32_t smem_u32(const void* p) {
    uint32_t a;
    asm("{ .reg .u64 t; cvta.to.shared.u64 t, %1; cvt.u32.u64 %0, t; }"
        : "=r"(a) : "l"(p));
    return a;
}

__device__ __forceinline__ void cpasync16(uint32_t dst, const void* src) {
    asm volatile("cp.async.cg.shared.global [%0], [%1], 16;"
                 :: "r"(dst), "l"(src));
}
#define CP_COMMIT() asm volatile("cp.async.commit_group;" ::: "memory")
#define CP_WAIT1()  asm volatile("cp.async.wait_group 1;" ::: "memory")
#define CP_WAIT0()  asm volatile("cp.async.wait_group 0;" ::: "memory")

__device__ __forceinline__ void ldm4(uint32_t* r, uint32_t addr) {
    asm volatile("ldmatrix.sync.aligned.m8n8.x4.shared.b16 {%0,%1,%2,%3}, [%4];"
                 : "=r"(r[0]), "=r"(r[1]), "=r"(r[2]), "=r"(r[3]) : "r"(addr));
}

__device__ __forceinline__ void mma16816(float* c, const uint32_t* a,
                                         uint32_t b0, uint32_t b1) {
    asm volatile(
        "mma.sync.aligned.m16n8k16.row.col.f32.bf16.bf16.f32 "
        "{%0,%1,%2,%3}, {%4,%5,%6,%7}, {%8,%9}, {%0,%1,%2,%3};"
        : "+f"(c[0]), "+f"(c[1]), "+f"(c[2]), "+f"(c[3])
        : "r"(a[0]), "r"(a[1]), "r"(a[2]), "r"(a[3]), "r"(b0), "r"(b1));
}

__device__ __forceinline__ void bsplit(float x, __nv_bfloat16& h, __nv_bfloat16& l) {
    h = __float2bfloat16_rn(x);
    l = __float2bfloat16_rn(x - __bfloat162float(h));
}

// ---------------------------------------------------------------------------
// Split pass: q + 4 weights -> bf16 hi/lo
// ---------------------------------------------------------------------------
__global__ void __launch_bounds__(256) split_kernel(const float* __restrict__ q,
                                                    const float* __restrict__ wq,
                                                    const float* __restrict__ wk,
                                                    const float* __restrict__ wv,
                                                    const float* __restrict__ wo)
{
    const size_t i4 = (size_t)blockIdx.x * 256 + threadIdx.x;  // float4 index
    const float* src;
    __nv_bfloat16 *dhi, *dlo;
    size_t e;
    if (i4 < 1048576) {                       // q: 4M floats
        src = q; e = i4;
        dhi = g_Ahi; dlo = g_Alo;
    } else {
        const size_t r = i4 - 1048576;
        const int w = (int)(r >> 18);         // 262144 float4 per weight
        e = r & 262143;
        src = (w == 0) ? wq : (w == 1) ? wk : (w == 2) ? wv : wo;
        dhi = g_Whi + (size_t)w * DD * DD;
        dlo = g_Wlo + (size_t)w * DD * DD;
    }
    const float4 v = ((const float4*)src)[e];
    __nv_bfloat16 h[4], l[4];
    bsplit(v.x, h[0], l[0]); bsplit(v.y, h[1], l[1]);
    bsplit(v.z, h[2], l[2]); bsplit(v.w, h[3], l[3]);
    *(ushort4*)(dhi + e * 4) = make_ushort4(*(unsigned short*)&h[0], *(unsigned short*)&h[1],
                                            *(unsigned short*)&h[2], *(unsigned short*)&h[3]);
    *(ushort4*)(dlo + e * 4) = make_ushort4(*(unsigned short*)&l[0], *(unsigned short*)&l[1],
                                            *(unsigned short*)&l[2], *(unsigned short*)&l[3]);
}

// ---------------------------------------------------------------------------
// bf16 mma.sync GEMM with 2-term correction.
//   C[M,N] = A[M,K] @ W[N,K]^T (+bias). Tile 128x128, 256 thr, 8 warps (2Mx4N).
// ---------------------------------------------------------------------------
__device__ __forceinline__ void gemm_body(const __nv_bfloat16* __restrict__ Ahi,
                                          const __nv_bfloat16* __restrict__ Alo,
                                          const __nv_bfloat16* __restrict__ Whi,
                                          const __nv_bfloat16* __restrict__ Wlo,
                                          float* __restrict__ C,
                                          const float* __restrict__ bias)
{
    extern __shared__ char dsm[];
    const uint32_t sb = smem_u32(dsm);
    const int tid  = threadIdx.x;
    const int wid  = tid >> 5;
    const int lane = tid & 31;
    const int wm   = wid >> 2;        // 0..1
    const int wn   = wid & 3;         // 0..3
    const int brow = blockIdx.y * TM;
    const int bcol = blockIdx.x * TN;

    const __nv_bfloat16* Abase[2] = { Ahi + (size_t)brow * DD, Alo + (size_t)brow * DD };
    const __nv_bfloat16* Bbase[2] = { Whi + (size_t)bcol * DD, Wlo + (size_t)bcol * DD };

    float acc[4][4][4];
#pragma unroll
    for (int a = 0; a < 4; ++a)
#pragma unroll
        for (int b = 0; b < 4; ++b)
#pragma unroll
            for (int c = 0; c < 4; ++c) acc[a][b][c] = 0.f;

    auto issue = [&](int kc, int stg) {
#pragma unroll
        for (int arr = 0; arr < 4; ++arr) {
            const __nv_bfloat16* g = (arr < 2) ? Abase[arr] : Bbase[arr - 2];
            const uint32_t sdst = sb + stg * STAGE_BYTES + arr * 16384;
#pragma unroll
            for (int it = 0; it < 4; ++it) {
                const int id = tid + it * 256;     // 0..1023
                const int r = id >> 3, c = id & 7;
                const void* src = g + (size_t)r * DD + kc * KC + c * 8;
                const uint32_t dst = sdst + r * 128 + ((c ^ (r & 7)) << 4);
                cpasync16(dst, src);
            }
        }
        CP_COMMIT();
    };

    issue(0, 0);
    issue(1, 1);

    for (int kc = 0; kc < NCH; ++kc) {
        if (kc + 1 < NCH) CP_WAIT1(); else CP_WAIT0();
        __syncthreads();
        if (kc + 2 < NCH) issue(kc + 2, (kc + 2) % NSTAGE);

        const uint32_t st = sb + (kc % NSTAGE) * STAGE_BYTES;
#pragma unroll
        for (int kk = 0; kk < 4; ++kk) {           // 4 x k16 per chunk
            const int c16 = kk * 2 + (lane >> 4);
            uint32_t ah[4][4], al[4][4], bh[2][4], bl[2][4];
#pragma unroll
            for (int mi = 0; mi < 4; ++mi) {
                const int row = wm * 64 + mi * 16 + (lane & 15);
                const uint32_t off = row * 128 + ((c16 ^ (row & 7)) << 4);
                ldm4(ah[mi], st + OFF_AHI + off);
                ldm4(al[mi], st + OFF_ALO + off);
            }
#pragma unroll
            for (int nb = 0; nb < 2; ++nb) {
                const int row = wn * 32 + nb * 16 + (lane & 15);
                const uint32_t off = row * 128 + ((c16 ^ (row & 7)) << 4);
                ldm4(bh[nb], st + OFF_BHI + off);
                ldm4(bl[nb], st + OFF_BLO + off);
            }
#pragma unroll
            for (int mi = 0; mi < 4; ++mi)
#pragma unroll
                for (int ni = 0; ni < 4; ++ni) {
                    const int nb = ni >> 1, s = ni & 1;
                    mma16816(acc[mi][ni], ah[mi], bh[nb][s], bh[nb][s + 2]);
                    mma16816(acc[mi][ni], al[mi], bh[nb][s], bh[nb][s + 2]);
                    mma16816(acc[mi][ni], ah[mi], bl[nb][s], bl[nb][s + 2]);
                }
        }
    }

    // Epilogue
#pragma unroll
    for (int mi = 0; mi < 4; ++mi) {
        const int row = brow + wm * 64 + mi * 16 + (lane >> 2);
#pragma unroll
        for (int ni = 0; ni < 4; ++ni) {
            const int col = bcol + wn * 32 + ni * 8 + (lane & 3) * 2;
            float2 v0 = make_float2(acc[mi][ni][0], acc[mi][ni][1]);
            float2 v1 = make_float2(acc[mi][ni][2], acc[mi][ni][3]);
            if (bias) {
                const float b0 = bias[col], b1 = bias[col + 1];
                v0.x += b0; v0.y += b1; v1.x += b0; v1.y += b1;
            }
            *(float2*)&C[(size_t)row * DD + col]       = v0;
            *(float2*)&C[(size_t)(row + 8) * DD + col] = v1;
        }
    }
}

__global__ void __launch_bounds__(256, 1) qkv_bf()
{
    const int z = blockIdx.z;
    float* Cc = (z == 0) ? g_Q : ((z == 1) ? g_K : g_V);
    gemm_body(g_Ahi, g_Alo,
              g_Whi + (size_t)z * DD * DD, g_Wlo + (size_t)z * DD * DD,
              Cc, nullptr);
}

__global__ void __launch_bounds__(256, 1) out_bf(const float* __restrict__ bo,
                                                 float* __restrict__ out)
{
    gemm_body(g_Chi, g_Clo,
              g_Whi + (size_t)3 * DD * DD, g_Wlo + (size_t)3 * DD * DD,
              out, bo);
}

// ---------------------------------------------------------------------------
// SMEM-tiled local-window attention. Block = 64 queries x (b,h).
// K/V window (128 rows x 64) staged in SMEM; warp-per-query online softmax.
// Writes context pre-split to bf16 hi/lo; optional attn band scatter.
// ---------------------------------------------------------------------------
__global__ void __launch_bounds__(256) attn_blk(float* __restrict__ attn_out)
{
    extern __shared__ float s[];
    float* Ks = s;                    // 128*64
    float* Vs = s + AROWS * 64;       // 128*64
    float* sc = s + AROWS * 128;      // 8*68

    const int tid  = threadIdx.x;
    const int warp = tid >> 5;
    const int lane = tid & 31;
    const int q0   = blockIdx.x * BQ;
    const int bh   = blockIdx.y;
    const int h    = bh & (HH - 1);
    const int b    = bh >> 4;
    const int jbase = q0 - 32;

    const float* Kg = g_K + (size_t)b * SS * DD + h * 64;
    const float* Vg = g_V + (size_t)b * SS * DD + h * 64;

    for (int idx = tid; idx < AROWS * 16; idx += 256) {
        const int r = idx >> 4, c4 = (idx & 15) * 4;
        const int j = jbase + r;
        if (j >= 0 && j < SS) {
            *(float4*)&Ks[r * 64 + c4] = *(const float4*)&Kg[(size_t)j * DD + c4];
            *(float4*)&Vs[r * 64 + c4] = *(const float4*)&Vg[(size_t)j * DD + c4];
        }
    }
    __syncthreads();

    for (int qi = 0; qi < 8; ++qi) {
        const int i = q0 + warp * 8 + qi;
        const float* Qr = g_Q + ((size_t)(b * SS + i)) * DD + h * 64;
        const float qv0 = Qr[lane];
        const float qv1 = Qr[lane + 32];
        const int jlo = max(0, i - 32);
        const int jhi = min(SS - 1, i + 32);

        float m = -1e30f, ssum = 0.f, a0 = 0.f, a1 = 0.f;
        for (int j = jlo; j <= jhi; ++j) {
            const float* Kr = &Ks[(j - jbase) * 64];
            float p = qv0 * Kr[lane] + qv1 * Kr[lane + 32];
#pragma unroll
            for (int off = 16; off; off >>= 1) p += __shfl_xor_sync(0xffffffffu, p, off);
            const float sv = p * 0.125f;
            if (attn_out) sc[warp * 68 + (j - jlo)] = sv;

            const float mn   = fmaxf(m, sv);
            const float corr = __expf(m - mn);
            const float e    = __expf(sv - mn);
            const float* Vr  = &Vs[(j - jbase) * 64];
            a0   = a0 * corr + e * Vr[lane];
            a1   = a1 * corr + e * Vr[lane + 32];
            ssum = ssum * corr + e;
            m    = mn;
        }

        const float inv = 1.f / ssum;
        const size_t co = ((size_t)(b * SS + i)) * DD + h * 64;
        bsplit(a0 * inv, g_Chi[co + lane],      g_Clo[co + lane]);
        bsplit(a1 * inv, g_Chi[co + lane + 32], g_Clo[co + lane + 32]);

        if (attn_out) {
            __syncwarp();
            float* rowp = attn_out + ((size_t)bh * SS + i) * SS;
            const int n = jhi - jlo + 1;
            for (int jj = lane; jj < n; jj += 32)
                rowp[jlo + jj] = __expf(sc[warp * 68 + jj] - m) * inv;
            __syncwarp();
        }
    }
}

// ---------------------------------------------------------------------------
extern "C" void kernel_launch(void* const* d_in, const int* in_sizes, int n_in,
                              void* d_out, int out_size)
{
    const float* q  = (const float*)d_in[0];
    const float* wq = (const float*)d_in[1];
    const float* wk = (const float*)d_in[2];
    const float* wv = (const float*)d_in[3];
    const float* wo = (const float*)d_in[4];
    const float* bo = (const float*)d_in[5];
    float* out = (float*)d_out;

    const size_t out_elems  = (size_t)BB * SS * DD;                 // 4,194,304
    const bool   write_attn = (size_t)out_size > out_elems;
    float* attn = out + out_elems;

    cudaFuncSetAttribute(qkv_bf,   cudaFuncAttributeMaxDynamicSharedMemorySize, GEMM_SMEM);
    cudaFuncSetAttribute(out_bf,   cudaFuncAttributeMaxDynamicSharedMemorySize, GEMM_SMEM);
    cudaFuncSetAttribute(attn_blk, cudaFuncAttributeMaxDynamicSharedMemorySize, ATT_SMEM);

    // 1) split q + weights into bf16 hi/lo
    split_kernel<<<8192, 256>>>(q, wq, wk, wv, wo);

    // 2) QKV projections (HMMA bf16 2-term)
    dim3 gq3(DD / TN, MM / TM, 3);
    qkv_bf<<<gq3, 256, GEMM_SMEM>>>();

    if (write_attn) {
        cudaMemsetAsync(attn, 0, (size_t)BB * HH * SS * SS * sizeof(float));
    }

    // 3) local attention (SMEM-tiled), writes split context
    dim3 ga(SS / BQ, BB * HH);
    attn_blk<<<ga, 256, ATT_SMEM>>>(write_attn ? attn : nullptr);

    // 4) output projection + bias
    dim3 go(DD / TN, MM / TM, 1);
    out_bf<<<go, 256, GEMM_SMEM>>>(bo, out);
}

// round 4
// speedup vs baseline: 2.1990x; 1.2756x over previous
#include <cuda_runtime.h>
#include <cuda_bf16.h>
#include <cstdint>

#define BB 2
#define SS 2048
#define DD 1024
#define HH 16
#define MM (BB*SS)             // 4096

// GEMM tiling: 128x128 tile, K-chunk 32 (64B rows, SW64-style swizzle)
#define TM 128
#define TN 128
#define KC 32
#define NCH (DD/KC)            // 32
#define NSTAGE 3
#define ARR_BYTES 8192         // 128 rows x 64B
#define STAGE_BYTES 32768
#define OFF_AHI 0
#define OFF_ALO 8192
#define OFF_BHI 16384
#define OFF_BLO 24576
#define GEMM_SMEM (NSTAGE*STAGE_BYTES)   // 98304 -> 2 CTAs/SM

// Attention tiling
#define BQ 64
#define AROWS 128
#define AST 66                 // smem row stride (floats): 8B-aligned, conflict-free
#define ATT_SMEM ((AROWS*AST*2 + BQ*AST + 8*68)*4)   // 86656 B

// ---------------------------------------------------------------------------
// Scratch (device globals: allocation-free rule)
// ---------------------------------------------------------------------------
__device__ float g_Q[(size_t)MM * DD];
__device__ float g_K[(size_t)MM * DD];
__device__ float g_V[(size_t)MM * DD];
__device__ __nv_bfloat16 g_Ahi[(size_t)MM * DD];
__device__ __nv_bfloat16 g_Alo[(size_t)MM * DD];
__device__ __nv_bfloat16 g_Whi[(size_t)4 * DD * DD];   // wq,wk,wv,wo
__device__ __nv_bfloat16 g_Wlo[(size_t)4 * DD * DD];
__device__ __nv_bfloat16 g_Chi[(size_t)MM * DD];
__device__ __nv_bfloat16 g_Clo[(size_t)MM * DD];

// ---------------------------------------------------------------------------
// Helpers
// ---------------------------------------------------------------------------
__device__ __forceinline__ uint32_t smem_u32(const void* p) {
    uint32_t a;
    asm("{ .reg .u64 t; cvta.to.shared.u64 t, %1; cvt.u32.u64 %0, t; }"
        : "=r"(a) : "l"(p));
    return a;
}

__device__ __forceinline__ void cpasync16(uint32_t dst, const void* src) {
    asm volatile("cp.async.cg.shared.global [%0], [%1], 16;"
                 :: "r"(dst), "l"(src));
}
#define CP_COMMIT() asm volatile("cp.async.commit_group;" ::: "memory")
#define CP_WAIT1()  asm volatile("cp.async.wait_group 1;" ::: "memory")
#define CP_WAIT0()  asm volatile("cp.async.wait_group 0;" ::: "memory")

__device__ __forceinline__ void ldm4(uint32_t* r, uint32_t addr) {
    asm volatile("ldmatrix.sync.aligned.m8n8.x4.shared.b16 {%0,%1,%2,%3}, [%4];"
                 : "=r"(r[0]), "=r"(r[1]), "=r"(r[2]), "=r"(r[3]) : "r"(addr));
}

__device__ __forceinline__ void mma16816(float* c, const uint32_t* a,
                                         uint32_t b0, uint32_t b1) {
    asm volatile(
        "mma.sync.aligned.m16n8k16.row.col.f32.bf16.bf16.f32 "
        "{%0,%1,%2,%3}, {%4,%5,%6,%7}, {%8,%9}, {%0,%1,%2,%3};"
        : "+f"(c[0]), "+f"(c[1]), "+f"(c[2]), "+f"(c[3])
        : "r"(a[0]), "r"(a[1]), "r"(a[2]), "r"(a[3]), "r"(b0), "r"(b1));
}

__device__ __forceinline__ void bsplit(float x, __nv_bfloat16& h, __nv_bfloat16& l) {
    h = __float2bfloat16_rn(x);
    l = __float2bfloat16_rn(x - __bfloat162float(h));
}

// ---------------------------------------------------------------------------
// Split pass: q + 4 weights -> bf16 hi/lo
// ---------------------------------------------------------------------------
__global__ void __launch_bounds__(256) split_kernel(const float* __restrict__ q,
                                                    const float* __restrict__ wq,
                                                    const float* __restrict__ wk,
                                                    const float* __restrict__ wv,
                                                    const float* __restrict__ wo)
{
    const size_t i4 = (size_t)blockIdx.x * 256 + threadIdx.x;  // float4 index
    const float* src;
    __nv_bfloat16 *dhi, *dlo;
    size_t e;
    if (i4 < 1048576) {                       // q: 4M floats
        src = q; e = i4;
        dhi = g_Ahi; dlo = g_Alo;
    } else {
        const size_t r = i4 - 1048576;
        const int w = (int)(r >> 18);         // 262144 float4 per weight
        e = r & 262143;
        src = (w == 0) ? wq : (w == 1) ? wk : (w == 2) ? wv : wo;
        dhi = g_Whi + (size_t)w * DD * DD;
        dlo = g_Wlo + (size_t)w * DD * DD;
    }
    const float4 v = ((const float4*)src)[e];
    __nv_bfloat16 h[4], l[4];
    bsplit(v.x, h[0], l[0]); bsplit(v.y, h[1], l[1]);
    bsplit(v.z, h[2], l[2]); bsplit(v.w, h[3], l[3]);
    *(ushort4*)(dhi + e * 4) = make_ushort4(*(unsigned short*)&h[0], *(unsigned short*)&h[1],
                                            *(unsigned short*)&h[2], *(unsigned short*)&h[3]);
    *(ushort4*)(dlo + e * 4) = make_ushort4(*(unsigned short*)&l[0], *(unsigned short*)&l[1],
                                            *(unsigned short*)&l[2], *(unsigned short*)&l[3]);
}

// ---------------------------------------------------------------------------
// bf16 mma.sync GEMM, 2-term correction, KC=32, 2 CTAs/SM.
// ---------------------------------------------------------------------------
__device__ __forceinline__ void gemm_body(const __nv_bfloat16* __restrict__ Ahi,
                                          const __nv_bfloat16* __restrict__ Alo,
                                          const __nv_bfloat16* __restrict__ Whi,
                                          const __nv_bfloat16* __restrict__ Wlo,
                                          float* __restrict__ C,
                                          const float* __restrict__ bias)
{
    extern __shared__ char dsm[];
    const uint32_t sb = smem_u32(dsm);
    const int tid  = threadIdx.x;
    const int wid  = tid >> 5;
    const int lane = tid & 31;
    const int wm   = wid >> 2;        // 0..1
    const int wn   = wid & 3;         // 0..3
    const int brow = blockIdx.y * TM;
    const int bcol = blockIdx.x * TN;

    const __nv_bfloat16* Abase[2] = { Ahi + (size_t)brow * DD, Alo + (size_t)brow * DD };
    const __nv_bfloat16* Bbase[2] = { Whi + (size_t)bcol * DD, Wlo + (size_t)bcol * DD };

    float acc[4][4][4];
#pragma unroll
    for (int a = 0; a < 4; ++a)
#pragma unroll
        for (int b = 0; b < 4; ++b)
#pragma unroll
            for (int c = 0; c < 4; ++c) acc[a][b][c] = 0.f;

    auto issue = [&](int kc, int stg) {
#pragma unroll
        for (int arr = 0; arr < 4; ++arr) {
            const __nv_bfloat16* g = (arr < 2) ? Abase[arr] : Bbase[arr - 2];
            const uint32_t sdst = sb + stg * STAGE_BYTES + arr * ARR_BYTES;
#pragma unroll
            for (int it = 0; it < 2; ++it) {
                const int id = tid + it * 256;     // 0..511
                const int r = id >> 2, c = id & 3;
                const void* src = g + (size_t)r * DD + kc * KC + c * 8;
                const uint32_t dst = sdst + r * 64 + ((c ^ ((r >> 1) & 3)) << 4);
                cpasync16(dst, src);
            }
        }
        CP_COMMIT();
    };

    issue(0, 0);
    issue(1, 1);

    for (int kc = 0; kc < NCH; ++kc) {
        if (kc + 1 < NCH) CP_WAIT1(); else CP_WAIT0();
        __syncthreads();
        if (kc + 2 < NCH) issue(kc + 2, (kc + 2) % NSTAGE);

        const uint32_t st = sb + (kc % NSTAGE) * STAGE_BYTES;
#pragma unroll
        for (int kk = 0; kk < 2; ++kk) {           // 2 x k16 per chunk
            const int c16 = kk * 2 + (lane >> 4);  // 16B chunk 0..3
            uint32_t aoff[4], boff[2];
#pragma unroll
            for (int mi = 0; mi < 4; ++mi) {
                const int row = wm * 64 + mi * 16 + (lane & 15);
                aoff[mi] = row * 64 + ((c16 ^ ((row >> 1) & 3)) << 4);
            }
#pragma unroll
            for (int nb = 0; nb < 2; ++nb) {
                const int row = wn * 32 + nb * 16 + (lane & 15);
                boff[nb] = row * 64 + ((c16 ^ ((row >> 1) & 3)) << 4);
            }
            uint32_t ah[4][4], bh[2][4];
#pragma unroll
            for (int mi = 0; mi < 4; ++mi) ldm4(ah[mi], st + OFF_AHI + aoff[mi]);
#pragma unroll
            for (int nb = 0; nb < 2; ++nb) ldm4(bh[nb], st + OFF_BHI + boff[nb]);
            // hi*hi while lo fragments load below
#pragma unroll
            for (int mi = 0; mi < 4; ++mi)
#pragma unroll
                for (int ni = 0; ni < 4; ++ni) {
                    const int nb = ni >> 1, s = ni & 1;
                    mma16816(acc[mi][ni], ah[mi], bh[nb][s], bh[nb][s + 2]);
                }
            uint32_t al[4][4], bl[2][4];
#pragma unroll
            for (int mi = 0; mi < 4; ++mi) ldm4(al[mi], st + OFF_ALO + aoff[mi]);
#pragma unroll
            for (int nb = 0; nb < 2; ++nb) ldm4(bl[nb], st + OFF_BLO + boff[nb]);
#pragma unroll
            for (int mi = 0; mi < 4; ++mi)
#pragma unroll
                for (int ni = 0; ni < 4; ++ni) {
                    const int nb = ni >> 1, s = ni & 1;
                    mma16816(acc[mi][ni], al[mi], bh[nb][s], bh[nb][s + 2]);
                    mma16816(acc[mi][ni], ah[mi], bl[nb][s], bl[nb][s + 2]);
                }
        }
    }

    // Epilogue
#pragma unroll
    for (int mi = 0; mi < 4; ++mi) {
        const int row = brow + wm * 64 + mi * 16 + (lane >> 2);
#pragma unroll
        for (int ni = 0; ni < 4; ++ni) {
            const int col = bcol + wn * 32 + ni * 8 + (lane & 3) * 2;
            float2 v0 = make_float2(acc[mi][ni][0], acc[mi][ni][1]);
            float2 v1 = make_float2(acc[mi][ni][2], acc[mi][ni][3]);
            if (bias) {
                const float b0 = bias[col], b1 = bias[col + 1];
                v0.x += b0; v0.y += b1; v1.x += b0; v1.y += b1;
            }
            *(float2*)&C[(size_t)row * DD + col]       = v0;
            *(float2*)&C[(size_t)(row + 8) * DD + col] = v1;
        }
    }
}

__global__ void __launch_bounds__(256, 2) qkv_bf()
{
    const int z = blockIdx.z;
    float* Cc = (z == 0) ? g_Q : ((z == 1) ? g_K : g_V);
    gemm_body(g_Ahi, g_Alo,
              g_Whi + (size_t)z * DD * DD, g_Wlo + (size_t)z * DD * DD,
              Cc, nullptr);
}

__global__ void __launch_bounds__(256, 2) out_bf(const float* __restrict__ bo,
                                                 float* __restrict__ out)
{
    gemm_body(g_Chi, g_Clo,
              g_Whi + (size_t)3 * DD * DD, g_Wlo + (size_t)3 * DD * DD,
              out, bo);
}

// ---------------------------------------------------------------------------
// Local-window attention, lane-per-key. Block = 64 queries x (b,h).
// Q/K/V tiles in SMEM (stride 66); per query: lane l scores keys jlo+l,
// jlo+l+32 (+ broadcast key 64), one max+sum warp reduction, probs via SMEM,
// then dim-parallel P.V. Writes context pre-split bf16 hi/lo + band scatter.
// ---------------------------------------------------------------------------
__global__ void __launch_bounds__(256) attn_blk(float* __restrict__ attn_out)
{
    extern __shared__ float s[];
    float* Ks = s;                         // 128*66
    float* Vs = Ks + AROWS * AST;          // 128*66
    float* Qs = Vs + AROWS * AST;          // 64*66
    float* ps = Qs + BQ * AST;             // 8*68

    const int tid  = threadIdx.x;
    const int warp = tid >> 5;
    const int lane = tid & 31;
    const int q0   = blockIdx.x * BQ;
    const int bh   = blockIdx.y;
    const int h    = bh & (HH - 1);
    const int b    = bh >> 4;
    const int jbase = q0 - 32;

    const float* Kg = g_K + (size_t)b * SS * DD + h * 64;
    const float* Vg = g_V + (size_t)b * SS * DD + h * 64;
    const float* Qg = g_Q + ((size_t)(b * SS + q0)) * DD + h * 64;

    for (int idx = tid; idx < AROWS * 16; idx += 256) {
        const int r = idx >> 4, c4 = (idx & 15) * 4;
        const int j = jbase + r;
        if (j >= 0 && j < SS) {
            const float4 kv = *(const float4*)&Kg[(size_t)j * DD + c4];
            const float4 vv = *(const float4*)&Vg[(size_t)j * DD + c4];
            const int o = r * AST + c4;
            *(float2*)&Ks[o]     = make_float2(kv.x, kv.y);
            *(float2*)&Ks[o + 2] = make_float2(kv.z, kv.w);
            *(float2*)&Vs[o]     = make_float2(vv.x, vv.y);
            *(float2*)&Vs[o + 2] = make_float2(vv.z, vv.w);
        }
    }
    for (int idx = tid; idx < BQ * 16; idx += 256) {
        const int r = idx >> 4, c4 = (idx & 15) * 4;
        const float4 qv = *(const float4*)&Qg[(size_t)r * DD + c4];
        const int o = r * AST + c4;
        *(float2*)&Qs[o]     = make_float2(qv.x, qv.y);
        *(float2*)&Qs[o + 2] = make_float2(qv.z, qv.w);
    }
    __syncthreads();

    float* pw = &ps[warp * 68];

    for (int qi = 0; qi < 8; ++qi) {
        const int qq = warp * 8 + qi;
        const int i  = q0 + qq;
        const int jlo = max(0, i - 32);
        const int jhi = min(SS - 1, i + 32);
        const int n   = jhi - jlo + 1;          // 33..65
        const int rbase = jlo - jbase;          // 0..63 (or 32 at left edge)

        const float* Qr = &Qs[qq * AST];
        const float* K0 = &Ks[(rbase + lane) * AST];
        const float* K1 = &Ks[(rbase + lane + 32) * AST];
        const float* K2 = &Ks[(rbase + 64) * AST];

        float s0 = 0.f, s1 = 0.f, s2 = 0.f;
#pragma unroll
        for (int d = 0; d < 64; d += 2) {
            const float2 q2 = *(const float2*)&Qr[d];
            const float2 k0 = *(const float2*)&K0[d];
            const float2 k1 = *(const float2*)&K1[d];
            const float2 k2 = *(const float2*)&K2[d];
            s0 = fmaf(q2.x, k0.x, fmaf(q2.y, k0.y, s0));
            s1 = fmaf(q2.x, k1.x, fmaf(q2.y, k1.y, s1));
            s2 = fmaf(q2.x, k2.x, fmaf(q2.y, k2.y, s2));
        }
        s0 *= 0.125f; s1 *= 0.125f; s2 *= 0.125f;

        const bool v1 = (lane + 32) < n;
        const bool v2 = (n == 65);

        float m = s0;
        if (v1) m = fmaxf(m, s1);
        if (v2) m = fmaxf(m, s2);
#pragma unroll
        for (int off = 16; off; off >>= 1) m = fmaxf(m, __shfl_xor_sync(0xffffffffu, m, off));

        const float e0 = __expf(s0 - m);
        const float e1 = v1 ? __expf(s1 - m) : 0.f;
        const float e2 = v2 ? __expf(s2 - m) : 0.f;
        float ssum = e0 + e1 + ((lane == 0) ? e2 : 0.f);
#pragma unroll
        for (int off = 16; off; off >>= 1) ssum += __shfl_xor_sync(0xffffffffu, ssum, off);
        const float inv = 1.f / ssum;

        pw[lane] = e0 * inv;
        if (v1) pw[lane + 32] = e1 * inv;
        if (lane == 0 && v2) pw[64] = e2 * inv;
        __syncwarp();

        if (attn_out) {
            float* rowp = attn_out + ((size_t)bh * SS + i) * SS + jlo;
            rowp[lane] = e0 * inv;
            if (v1) rowp[lane + 32] = e1 * inv;
            if (lane == 0 && v2) rowp[64] = e2 * inv;
        }

        float a0 = 0.f, a1 = 0.f;
        const float* Vr = &Vs[rbase * AST];
        for (int jj = 0; jj < n; ++jj) {
            const float p = pw[jj];
            a0 = fmaf(p, Vr[lane], a0);
            a1 = fmaf(p, Vr[lane + 32], a1);
            Vr += AST;
        }

        const size_t co = ((size_t)(b * SS + i)) * DD + h * 64;
        bsplit(a0, g_Chi[co + lane],      g_Clo[co + lane]);
        bsplit(a1, g_Chi[co + lane + 32], g_Clo[co + lane + 32]);
        __syncwarp();
    }
}

// ---------------------------------------------------------------------------
extern "C" void kernel_launch(void* const* d_in, const int* in_sizes, int n_in,
                              void* d_out, int out_size)
{
    const float* q  = (const float*)d_in[0];
    const float* wq = (const float*)d_in[1];
    const float* wk = (const float*)d_in[2];
    const float* wv = (const float*)d_in[3];
    const float* wo = (const float*)d_in[4];
    const float* bo = (const float*)d_in[5];
    float* out = (float*)d_out;

    const size_t out_elems  = (size_t)BB * SS * DD;                 // 4,194,304
    const bool   write_attn = (size_t)out_size > out_elems;
    float* attn = out + out_elems;

    // One-time host objects (created on the uncaptured correctness call)
    static cudaStream_t s2 = nullptr;
    static cudaEvent_t evF = nullptr, evJ = nullptr;
    if (!s2) {
        cudaStreamCreateWithFlags(&s2, cudaStreamNonBlocking);
        cudaEventCreateWithFlags(&evF, cudaEventDisableTiming);
        cudaEventCreateWithFlags(&evJ, cudaEventDisableTiming);
    }

    cudaFuncSetAttribute(qkv_bf,   cudaFuncAttributeMaxDynamicSharedMemorySize, GEMM_SMEM);
    cudaFuncSetAttribute(out_bf,   cudaFuncAttributeMaxDynamicSharedMemorySize, GEMM_SMEM);
    cudaFuncSetAttribute(attn_blk, cudaFuncAttributeMaxDynamicSharedMemorySize, ATT_SMEM);

    // Fork: zero the attn band region on a side stream, overlapped with
    // split + qkv. Joined before the attn kernel scatters the band.
    if (write_attn) {
        cudaEventRecord(evF, 0);
        cudaStreamWaitEvent(s2, evF, 0);
        cudaMemsetAsync(attn, 0, (size_t)BB * HH * SS * SS * sizeof(float), s2);
        cudaEventRecord(evJ, s2);
    }

    // 1) split q + weights into bf16 hi/lo
    split_kernel<<<8192, 256>>>(q, wq, wk, wv, wo);

    // 2) QKV projections
    dim3 gq3(DD / TN, MM / TM, 3);
    qkv_bf<<<gq3, 256, GEMM_SMEM>>>();

    if (write_attn) cudaStreamWaitEvent(0, evJ, 0);

    // 3) local attention (lane-per-key), writes split context + band
    dim3 ga(SS / BQ, BB * HH);
    attn_blk<<<ga, 256, ATT_SMEM>>>(write_attn ? attn : nullptr);

    // 4) output projection + bias
    dim3 go(DD / TN, MM / TM, 1);
    out_bf<<<go, 256, GEMM_SMEM>>>(bo, out);
}